// round 2
// baseline (speedup 1.0000x reference)
#include <cuda_runtime.h>

#define B_ROWS  16384
#define IN_DIM  1024
#define OUT_DIM 768

// 48 MB scratch for z = x @ W^T (allocation-free rule: __device__ global).
// Explicit 16B alignment so float4 access is guaranteed legal.
__device__ __align__(16) float g_z[B_ROWS * OUT_DIM];

// ---------------------------------------------------------------------------
// SGEMM (NT): C[M,N] = A[M,K] * W[N,K]^T      M=16384, N=768, K=1024, fp32
// BM=128, BN=128, BK=16, 256 threads, 8x8 micro-tile
// ---------------------------------------------------------------------------
__global__ __launch_bounds__(256) void sgemm_nt_kernel(const float* __restrict__ A,
                                                       const float* __restrict__ W) {
    const int K = IN_DIM;
    __shared__ float As[16][132];   // [k][m], padded
    __shared__ float Bs[16][132];   // [k][n], padded

    const int tid = threadIdx.x;
    const int tx = tid & 15;        // 0..15  -> 8 cols each
    const int ty = tid >> 4;        // 0..15  -> 8 rows each
    const int bm = blockIdx.y * 128;
    const int bn = blockIdx.x * 128;

    const float* Aptr = A + (size_t)bm * K;
    const float* Wptr = W + (size_t)bn * K;

    float acc[8][8];
#pragma unroll
    for (int i = 0; i < 8; i++)
#pragma unroll
        for (int j = 0; j < 8; j++) acc[i][j] = 0.f;

    for (int k0 = 0; k0 < K; k0 += 16) {
        // load A tile: 128x16 = 512 float4, 2 per thread
#pragma unroll
        for (int i = 0; i < 2; i++) {
            int f    = tid + i * 256;
            int row  = f >> 2;            // 0..127
            int kc   = (f & 3) * 4;       // 0,4,8,12
            float4 v = *(const float4*)(Aptr + (size_t)row * K + k0 + kc);
            As[kc + 0][row] = v.x;
            As[kc + 1][row] = v.y;
            As[kc + 2][row] = v.z;
            As[kc + 3][row] = v.w;
        }
        // load W tile: 128x16
#pragma unroll
        for (int i = 0; i < 2; i++) {
            int f    = tid + i * 256;
            int row  = f >> 2;
            int kc   = (f & 3) * 4;
            float4 v = *(const float4*)(Wptr + (size_t)row * K + k0 + kc);
            Bs[kc + 0][row] = v.x;
            Bs[kc + 1][row] = v.y;
            Bs[kc + 2][row] = v.z;
            Bs[kc + 3][row] = v.w;
        }
        __syncthreads();

#pragma unroll
        for (int kk = 0; kk < 16; kk++) {
            float a[8], b[8];
            *(float4*)&a[0] = *(const float4*)&As[kk][ty * 8];
            *(float4*)&a[4] = *(const float4*)&As[kk][ty * 8 + 4];
            *(float4*)&b[0] = *(const float4*)&Bs[kk][tx * 8];
            *(float4*)&b[4] = *(const float4*)&Bs[kk][tx * 8 + 4];
#pragma unroll
            for (int i = 0; i < 8; i++)
#pragma unroll
                for (int j = 0; j < 8; j++) acc[i][j] = fmaf(a[i], b[j], acc[i][j]);
        }
        __syncthreads();
    }

#pragma unroll
    for (int i = 0; i < 8; i++) {
        int row = bm + ty * 8 + i;
        float* cp = g_z + (size_t)row * OUT_DIM + bn + tx * 8;
        *(float4*)(cp)     = make_float4(acc[i][0], acc[i][1], acc[i][2], acc[i][3]);
        *(float4*)(cp + 4) = make_float4(acc[i][4], acc[i][5], acc[i][6], acc[i][7]);
    }
}

// ---------------------------------------------------------------------------
// Batched Householder QR (LAPACK geqrf/orgqr convention) of 256x3 matrices.
// One warp per batch row. Lane l owns rows 8l..8l+7 (contiguous -> float4 I/O).
// ---------------------------------------------------------------------------
__device__ __forceinline__ float warp_sum(float v) {
#pragma unroll
    for (int o = 16; o > 0; o >>= 1) v += __shfl_xor_sync(0xffffffffu, v, o);
    return v;
}

__global__ __launch_bounds__(256) void qr_kernel(float* __restrict__ out) {
    const int warp = (blockIdx.x * blockDim.x + threadIdx.x) >> 5;
    const int lane = threadIdx.x & 31;
    if (warp >= B_ROWS) return;

    // load 24 contiguous floats per lane (rows 8*lane .. 8*lane+7, 3 cols each)
    float4 buf[6];
    const float4* zp = (const float4*)(g_z + (size_t)warp * OUT_DIM) + lane * 6;
#pragma unroll
    for (int i = 0; i < 6; i++) buf[i] = zp[i];
    float* bf = (float*)buf;

    float Mv[8][3];
#pragma unroll
    for (int r = 0; r < 8; r++)
#pragma unroll
        for (int j = 0; j < 3; j++) Mv[r][j] = bf[r * 3 + j];

    const int gr0 = lane * 8;
    float tau[3];

    // ---- geqrf: 3 Householder reflectors, LAPACK sign convention ----
#pragma unroll
    for (int k = 0; k < 3; k++) {
        float ss = 0.f;
#pragma unroll
        for (int r = 0; r < 8; r++) {
            int gr = gr0 + r;
            if (gr >= k) ss += Mv[r][k] * Mv[r][k];
        }
        ss = warp_sum(ss);
        // alpha = A[k][k]; rows 0..7 live on lane 0 (k < 3)
        float alpha = __shfl_sync(0xffffffffu, Mv[k][k], 0);
        float nrm = sqrtf(ss);
        float beta = (alpha >= 0.f) ? -nrm : nrm;          // -sign(alpha)*||x||
        float t = (nrm > 0.f) ? (beta - alpha) / beta : 0.f;
        tau[k] = t;
        float inv = (nrm > 0.f) ? 1.0f / (alpha - beta) : 0.f;
        // v: v[k]=1 (implicit), v[gr>k] = A[gr][k]*inv stored in place
#pragma unroll
        for (int r = 0; r < 8; r++) {
            int gr = gr0 + r;
            if (gr > k) Mv[r][k] *= inv;
        }
        // apply H = I - t*v*v^T to remaining columns
#pragma unroll
        for (int j = 0; j < 3; j++) {
            if (j <= k) continue;
            float d = 0.f;
#pragma unroll
            for (int r = 0; r < 8; r++) {
                int gr = gr0 + r;
                if (gr > k)       d += Mv[r][k] * Mv[r][j];
                else if (gr == k) d += Mv[r][j];
            }
            d = warp_sum(d);
            float td = t * d;
#pragma unroll
            for (int r = 0; r < 8; r++) {
                int gr = gr0 + r;
                if (gr > k)       Mv[r][j] -= td * Mv[r][k];
                else if (gr == k) Mv[r][j] -= td;
            }
        }
    }

    // ---- orgqr: Q = H0 H1 H2 * E(256x3) ----
    float Q[8][3];
#pragma unroll
    for (int r = 0; r < 8; r++)
#pragma unroll
        for (int j = 0; j < 3; j++) Q[r][j] = (gr0 + r == j) ? 1.f : 0.f;

#pragma unroll
    for (int k = 2; k >= 0; k--) {
        float d[3];
#pragma unroll
        for (int j = 0; j < 3; j++) {
            float s = 0.f;
#pragma unroll
            for (int r = 0; r < 8; r++) {
                int gr = gr0 + r;
                if (gr > k)       s += Mv[r][k] * Q[r][j];
                else if (gr == k) s += Q[r][j];
            }
            d[j] = warp_sum(s) * tau[k];
        }
#pragma unroll
        for (int j = 0; j < 3; j++) {
#pragma unroll
            for (int r = 0; r < 8; r++) {
                int gr = gr0 + r;
                if (gr > k)       Q[r][j] -= d[j] * Mv[r][k];
                else if (gr == k) Q[r][j] -= d[j];
            }
        }
    }

    // store 24 contiguous floats per lane
#pragma unroll
    for (int r = 0; r < 8; r++)
#pragma unroll
        for (int j = 0; j < 3; j++) bf[r * 3 + j] = Q[r][j];
    float4* op = (float4*)(out + (size_t)warp * OUT_DIM) + lane * 6;
#pragma unroll
    for (int i = 0; i < 6; i++) op[i] = buf[i];
}

// ---------------------------------------------------------------------------
extern "C" void kernel_launch(void* const* d_in, const int* in_sizes, int n_in,
                              void* d_out, int out_size) {
    const float* x = (const float*)d_in[0];   // (16384, 1024) fp32
    const float* W = (const float*)d_in[1];   // (768, 1024) fp32
    float* out = (float*)d_out;               // (16384, 768) fp32

    dim3 grid(OUT_DIM / 128, B_ROWS / 128);   // (6, 128)
    sgemm_nt_kernel<<<grid, 256>>>(x, W);

    int total_warps = B_ROWS;                 // one warp per batch row
    int threads = 256;
    int blocks = (total_warps * 32 + threads - 1) / threads;  // 2048
    qr_kernel<<<blocks, threads>>>(out);
}

// round 7
// speedup vs baseline: 2.1768x; 2.1768x over previous
#include <cuda_runtime.h>
#include <cuda_bf16.h>
#include <cstdint>

#define B_ROWS  16384
#define IN_DIM  1024
#define OUT_DIM 768

// ---------------- device scratch (allocation-free rule) ----------------
__device__ __align__(16) float         g_z[B_ROWS * OUT_DIM];      // 48 MB
__device__ __align__(16) __nv_bfloat16 g_xhi[B_ROWS * IN_DIM];     // 32 MB
__device__ __align__(16) __nv_bfloat16 g_xlo[B_ROWS * IN_DIM];     // 32 MB
__device__ __align__(16) __nv_bfloat16 g_whi[OUT_DIM * IN_DIM];    // 1.5 MB
__device__ __align__(16) __nv_bfloat16 g_wlo[OUT_DIM * IN_DIM];    // 1.5 MB

// ---------------- helpers ----------------
__device__ __forceinline__ uint32_t smem_u32(const void* p) {
    uint32_t a;
    asm("{ .reg .u64 t; cvta.to.shared.u64 t, %1; cvt.u32.u64 %0, t; }" : "=r"(a) : "l"(p));
    return a;
}
__device__ __forceinline__ void cp16(uint32_t dst, const void* src) {
    asm volatile("cp.async.cg.shared.global [%0], [%1], 16;" :: "r"(dst), "l"(src));
}
__device__ __forceinline__ void ldsm4(uint32_t* r, uint32_t addr) {
    asm volatile("ldmatrix.sync.aligned.m8n8.x4.shared.b16 {%0,%1,%2,%3}, [%4];"
                 : "=r"(r[0]), "=r"(r[1]), "=r"(r[2]), "=r"(r[3]) : "r"(addr));
}
__device__ __forceinline__ void mma16816(float* c, const uint32_t* a, const uint32_t* b) {
    asm volatile(
        "mma.sync.aligned.m16n8k16.row.col.f32.bf16.bf16.f32 "
        "{%0,%1,%2,%3}, {%4,%5,%6,%7}, {%8,%9}, {%0,%1,%2,%3};"
        : "+f"(c[0]), "+f"(c[1]), "+f"(c[2]), "+f"(c[3])
        : "r"(a[0]), "r"(a[1]), "r"(a[2]), "r"(a[3]), "r"(b[0]), "r"(b[1]));
}

__device__ __forceinline__ void split4(float4 v, __nv_bfloat162* hp, __nv_bfloat162* lp, int i) {
    __nv_bfloat16 h0 = __float2bfloat16_rn(v.x);
    __nv_bfloat16 h1 = __float2bfloat16_rn(v.y);
    __nv_bfloat16 h2 = __float2bfloat16_rn(v.z);
    __nv_bfloat16 h3 = __float2bfloat16_rn(v.w);
    __nv_bfloat16 l0 = __float2bfloat16_rn(v.x - __bfloat162float(h0));
    __nv_bfloat16 l1 = __float2bfloat16_rn(v.y - __bfloat162float(h1));
    __nv_bfloat16 l2 = __float2bfloat16_rn(v.z - __bfloat162float(h2));
    __nv_bfloat16 l3 = __float2bfloat16_rn(v.w - __bfloat162float(h3));
    hp[2 * i]     = __nv_bfloat162(h0, h1);
    hp[2 * i + 1] = __nv_bfloat162(h2, h3);
    lp[2 * i]     = __nv_bfloat162(l0, l1);
    lp[2 * i + 1] = __nv_bfloat162(l2, l3);
}

// split kernels write the __device__ globals directly (no cudaGetSymbolAddress)
__global__ __launch_bounds__(256) void split_x_kernel(const float* __restrict__ src) {
    int i = blockIdx.x * blockDim.x + threadIdx.x;
    if (i >= B_ROWS * IN_DIM / 4) return;
    split4(((const float4*)src)[i], (__nv_bfloat162*)g_xhi, (__nv_bfloat162*)g_xlo, i);
}
__global__ __launch_bounds__(256) void split_w_kernel(const float* __restrict__ src) {
    int i = blockIdx.x * blockDim.x + threadIdx.x;
    if (i >= OUT_DIM * IN_DIM / 4) return;
    split4(((const float4*)src)[i], (__nv_bfloat162*)g_whi, (__nv_bfloat162*)g_wlo, i);
}

// ---------------- bf16x3 GEMM via mma.sync ----------------
// CTA 128x128x16, 8 warps of 64x32, 3-stage cp.async pipeline, 48 KB smem.
#define BK      16
#define KITERS  (IN_DIM / BK)       // 64
#define TILE_B  (128 * BK * 2)      // 4096 B per tile
#define STAGE_B (4 * TILE_B)        // Ahi, Alo, Bhi, Blo = 16 KB
#define STAGES  3
#define SMEM_DYN (STAGES * STAGE_B) // 49152 B = 48 KB (default limit, no attribute needed)

// swizzled byte offset inside one tile: 32B rows, granule kg in 0..1
__device__ __forceinline__ uint32_t swz16(int row, int kg) {
    return (uint32_t)(row * 32 + ((kg ^ ((row >> 2) & 1)) << 4));
}

__device__ __forceinline__ void ld_tile(uint32_t dst, const __nv_bfloat16* src,
                                        int k0, int tid) {
    int r  = tid >> 1;          // 0..127
    int kg = tid & 1;           // 0..1
    cp16(dst + swz16(r, kg), src + (size_t)r * IN_DIM + k0 + kg * 8);
}

__global__ __launch_bounds__(256) void gemm_bf16x3_kernel() {
    extern __shared__ char dsm[];
    const int tid  = threadIdx.x;
    const int wid  = tid >> 5;
    const int lane = tid & 31;
    const int bm = blockIdx.y * 128;
    const int bn = blockIdx.x * 128;
    const int warpM = (wid >> 2) * 64;   // 0 or 64
    const int warpN = (wid & 3) * 32;    // 0,32,64,96

    const uint32_t sbase = smem_u32(dsm);

    const __nv_bfloat16* xh = g_xhi + (size_t)bm * IN_DIM;
    const __nv_bfloat16* xl = g_xlo + (size_t)bm * IN_DIM;
    const __nv_bfloat16* wh = g_whi + (size_t)bn * IN_DIM;
    const __nv_bfloat16* wl = g_wlo + (size_t)bn * IN_DIM;

    // prologue: fill stages 0 and 1
#pragma unroll
    for (int s = 0; s < 2; s++) {
        uint32_t sb = sbase + s * STAGE_B;
        ld_tile(sb + 0 * TILE_B, xh, s * BK, tid);
        ld_tile(sb + 1 * TILE_B, xl, s * BK, tid);
        ld_tile(sb + 2 * TILE_B, wh, s * BK, tid);
        ld_tile(sb + 3 * TILE_B, wl, s * BK, tid);
        asm volatile("cp.async.commit_group;" ::: "memory");
    }

    float acc[4][4][4];
#pragma unroll
    for (int m = 0; m < 4; m++)
#pragma unroll
        for (int n = 0; n < 4; n++)
#pragma unroll
            for (int q = 0; q < 4; q++) acc[m][n][q] = 0.f;

    // per-lane ldmatrix address components (m16n8k16 fragment maps)
    const int arow = warpM + (lane & 7) + ((lane >> 3) & 1) * 8;  // + matom*16
    const int akg  = lane >> 4;                                    // k-half 0/1
    const int brow = warpN + (lane & 7) + (lane >> 4) * 8;         // + npair*16
    const int bkg  = (lane >> 3) & 1;

    for (int i = 0; i < KITERS; i++) {
        const uint32_t sb = sbase + (i % STAGES) * STAGE_B;

        if (i == KITERS - 1) asm volatile("cp.async.wait_group 0;" ::: "memory");
        else                 asm volatile("cp.async.wait_group 1;" ::: "memory");
        __syncthreads();

        // prefetch i+2 into the slot freed by i-1
        if (i + 2 < KITERS) {
            uint32_t pb = sbase + ((i + 2) % STAGES) * STAGE_B;
            const int kn = (i + 2) * BK;
            ld_tile(pb + 0 * TILE_B, xh, kn, tid);
            ld_tile(pb + 1 * TILE_B, xl, kn, tid);
            ld_tile(pb + 2 * TILE_B, wh, kn, tid);
            ld_tile(pb + 3 * TILE_B, wl, kn, tid);
            asm volatile("cp.async.commit_group;" ::: "memory");
        }

        const uint32_t As = sb + 0 * TILE_B;
        const uint32_t Al = sb + 1 * TILE_B;
        const uint32_t Bs = sb + 2 * TILE_B;
        const uint32_t Bl = sb + 3 * TILE_B;

        uint32_t ahi[4][4], alo[4][4], bhi[2][4], blo[2][4];
#pragma unroll
        for (int m = 0; m < 4; m++) {
            int r = arow + m * 16;
            ldsm4(ahi[m], As + swz16(r, akg));
            ldsm4(alo[m], Al + swz16(r, akg));
        }
#pragma unroll
        for (int np = 0; np < 2; np++) {
            int r = brow + np * 16;
            ldsm4(bhi[np], Bs + swz16(r, bkg));
            ldsm4(blo[np], Bl + swz16(r, bkg));
        }
        // acc += Ahi*Bhi + Ahi*Blo + Alo*Bhi
#pragma unroll
        for (int m = 0; m < 4; m++)
#pragma unroll
            for (int np = 0; np < 2; np++)
#pragma unroll
                for (int h = 0; h < 2; h++) {
                    float* c = acc[m][np * 2 + h];
                    mma16816(c, ahi[m], &bhi[np][h * 2]);
                    mma16816(c, ahi[m], &blo[np][h * 2]);
                    mma16816(c, alo[m], &bhi[np][h * 2]);
                }
    }

    // epilogue: direct fp32 stores to g_z
#pragma unroll
    for (int m = 0; m < 4; m++) {
        int row = bm + warpM + m * 16 + (lane >> 2);
#pragma unroll
        for (int n = 0; n < 4; n++) {
            int col = bn + warpN + n * 8 + (lane & 3) * 2;
            *(float2*)(g_z + (size_t)row * OUT_DIM + col) =
                make_float2(acc[m][n][0], acc[m][n][1]);
            *(float2*)(g_z + (size_t)(row + 8) * OUT_DIM + col) =
                make_float2(acc[m][n][2], acc[m][n][3]);
        }
    }
}

// ---------------------------------------------------------------------------
// Batched Householder QR (LAPACK geqrf/orgqr) of 256x3 matrices. (unchanged)
// ---------------------------------------------------------------------------
__device__ __forceinline__ float warp_sum(float v) {
#pragma unroll
    for (int o = 16; o > 0; o >>= 1) v += __shfl_xor_sync(0xffffffffu, v, o);
    return v;
}

__global__ __launch_bounds__(256) void qr_kernel(float* __restrict__ out) {
    const int warp = (blockIdx.x * blockDim.x + threadIdx.x) >> 5;
    const int lane = threadIdx.x & 31;
    if (warp >= B_ROWS) return;

    float4 buf[6];
    const float4* zp = (const float4*)(g_z + (size_t)warp * OUT_DIM) + lane * 6;
#pragma unroll
    for (int i = 0; i < 6; i++) buf[i] = zp[i];
    float* bf = (float*)buf;

    float Mv[8][3];
#pragma unroll
    for (int r = 0; r < 8; r++)
#pragma unroll
        for (int j = 0; j < 3; j++) Mv[r][j] = bf[r * 3 + j];

    const int gr0 = lane * 8;
    float tau[3];

#pragma unroll
    for (int k = 0; k < 3; k++) {
        float ss = 0.f;
#pragma unroll
        for (int r = 0; r < 8; r++) {
            int gr = gr0 + r;
            if (gr >= k) ss += Mv[r][k] * Mv[r][k];
        }
        ss = warp_sum(ss);
        float alpha = __shfl_sync(0xffffffffu, Mv[k][k], 0);
        float nrm = sqrtf(ss);
        float beta = (alpha >= 0.f) ? -nrm : nrm;
        float t = (nrm > 0.f) ? (beta - alpha) / beta : 0.f;
        tau[k] = t;
        float inv = (nrm > 0.f) ? 1.0f / (alpha - beta) : 0.f;
#pragma unroll
        for (int r = 0; r < 8; r++) {
            int gr = gr0 + r;
            if (gr > k) Mv[r][k] *= inv;
        }
#pragma unroll
        for (int j = 0; j < 3; j++) {
            if (j <= k) continue;
            float d = 0.f;
#pragma unroll
            for (int r = 0; r < 8; r++) {
                int gr = gr0 + r;
                if (gr > k)       d += Mv[r][k] * Mv[r][j];
                else if (gr == k) d += Mv[r][j];
            }
            d = warp_sum(d);
            float td = t * d;
#pragma unroll
            for (int r = 0; r < 8; r++) {
                int gr = gr0 + r;
                if (gr > k)       Mv[r][j] -= td * Mv[r][k];
                else if (gr == k) Mv[r][j] -= td;
            }
        }
    }

    float Q[8][3];
#pragma unroll
    for (int r = 0; r < 8; r++)
#pragma unroll
        for (int j = 0; j < 3; j++) Q[r][j] = (gr0 + r == j) ? 1.f : 0.f;

#pragma unroll
    for (int k = 2; k >= 0; k--) {
        float d[3];
#pragma unroll
        for (int j = 0; j < 3; j++) {
            float s = 0.f;
#pragma unroll
            for (int r = 0; r < 8; r++) {
                int gr = gr0 + r;
                if (gr > k)       s += Mv[r][k] * Q[r][j];
                else if (gr == k) s += Q[r][j];
            }
            d[j] = warp_sum(s) * tau[k];
        }
#pragma unroll
        for (int j = 0; j < 3; j++) {
#pragma unroll
            for (int r = 0; r < 8; r++) {
                int gr = gr0 + r;
                if (gr > k)       Q[r][j] -= d[j] * Mv[r][k];
                else if (gr == k) Q[r][j] -= d[j];
            }
        }
    }

#pragma unroll
    for (int r = 0; r < 8; r++)
#pragma unroll
        for (int j = 0; j < 3; j++) bf[r * 3 + j] = Q[r][j];
    float4* op = (float4*)(out + (size_t)warp * OUT_DIM) + lane * 6;
#pragma unroll
    for (int i = 0; i < 6; i++) op[i] = buf[i];
}

// ---------------------------------------------------------------------------
// kernel_launch: ONLY kernel launches — no runtime API calls of any kind.
// ---------------------------------------------------------------------------
extern "C" void kernel_launch(void* const* d_in, const int* in_sizes, int n_in,
                              void* d_out, int out_size) {
    const float* x = (const float*)d_in[0];   // (16384, 1024) fp32
    const float* W = (const float*)d_in[1];   // (768, 1024) fp32
    float* out = (float*)d_out;               // (16384, 768) fp32

    split_x_kernel<<<(B_ROWS * IN_DIM / 4 + 255) / 256, 256>>>(x);
    split_w_kernel<<<(OUT_DIM * IN_DIM / 4 + 255) / 256, 256>>>(W);

    dim3 grid(OUT_DIM / 128, B_ROWS / 128);   // (6, 128)
    gemm_bf16x3_kernel<<<grid, 256, SMEM_DYN>>>();

    qr_kernel<<<2048, 256>>>(out);
}

// round 8
// speedup vs baseline: 2.2329x; 1.0257x over previous
#include <cuda_runtime.h>
#include <cuda_bf16.h>
#include <cstdint>

#define B_ROWS  16384
#define IN_DIM  1024
#define OUT_DIM 768

// ---------------- device scratch (allocation-free rule) ----------------
__device__ __align__(16) float         g_z[B_ROWS * OUT_DIM];      // 48 MB
__device__ __align__(16) __nv_bfloat16 g_xhi[B_ROWS * IN_DIM];     // 32 MB
__device__ __align__(16) __nv_bfloat16 g_xlo[B_ROWS * IN_DIM];     // 32 MB
__device__ __align__(16) __nv_bfloat16 g_whi[OUT_DIM * IN_DIM];    // 1.5 MB
__device__ __align__(16) __nv_bfloat16 g_wlo[OUT_DIM * IN_DIM];    // 1.5 MB

// ---------------- helpers ----------------
__device__ __forceinline__ uint32_t smem_u32(const void* p) {
    uint32_t a;
    asm("{ .reg .u64 t; cvta.to.shared.u64 t, %1; cvt.u32.u64 %0, t; }" : "=r"(a) : "l"(p));
    return a;
}
__device__ __forceinline__ void cp16(uint32_t dst, const void* src) {
    asm volatile("cp.async.cg.shared.global [%0], [%1], 16;" :: "r"(dst), "l"(src));
}
__device__ __forceinline__ void ldsm4(uint32_t* r, uint32_t addr) {
    asm volatile("ldmatrix.sync.aligned.m8n8.x4.shared.b16 {%0,%1,%2,%3}, [%4];"
                 : "=r"(r[0]), "=r"(r[1]), "=r"(r[2]), "=r"(r[3]) : "r"(addr));
}
__device__ __forceinline__ void mma16816(float* c, const uint32_t* a, const uint32_t* b) {
    asm volatile(
        "mma.sync.aligned.m16n8k16.row.col.f32.bf16.bf16.f32 "
        "{%0,%1,%2,%3}, {%4,%5,%6,%7}, {%8,%9}, {%0,%1,%2,%3};"
        : "+f"(c[0]), "+f"(c[1]), "+f"(c[2]), "+f"(c[3])
        : "r"(a[0]), "r"(a[1]), "r"(a[2]), "r"(a[3]), "r"(b[0]), "r"(b[1]));
}

__device__ __forceinline__ void split4(float4 v, __nv_bfloat162* hp, __nv_bfloat162* lp, int i) {
    __nv_bfloat16 h0 = __float2bfloat16_rn(v.x);
    __nv_bfloat16 h1 = __float2bfloat16_rn(v.y);
    __nv_bfloat16 h2 = __float2bfloat16_rn(v.z);
    __nv_bfloat16 h3 = __float2bfloat16_rn(v.w);
    __nv_bfloat16 l0 = __float2bfloat16_rn(v.x - __bfloat162float(h0));
    __nv_bfloat16 l1 = __float2bfloat16_rn(v.y - __bfloat162float(h1));
    __nv_bfloat16 l2 = __float2bfloat16_rn(v.z - __bfloat162float(h2));
    __nv_bfloat16 l3 = __float2bfloat16_rn(v.w - __bfloat162float(h3));
    hp[2 * i]     = __nv_bfloat162(h0, h1);
    hp[2 * i + 1] = __nv_bfloat162(h2, h3);
    lp[2 * i]     = __nv_bfloat162(l0, l1);
    lp[2 * i + 1] = __nv_bfloat162(l2, l3);
}

// one launch covers x and W (W indices appended after x's)
#define N4X (B_ROWS * IN_DIM / 4)
#define N4W (OUT_DIM * IN_DIM / 4)
__global__ __launch_bounds__(256) void split_all_kernel(const float* __restrict__ x,
                                                        const float* __restrict__ W) {
    int i = blockIdx.x * blockDim.x + threadIdx.x;
    if (i < N4X) {
        split4(((const float4*)x)[i], (__nv_bfloat162*)g_xhi, (__nv_bfloat162*)g_xlo, i);
    } else if (i < N4X + N4W) {
        int j = i - N4X;
        split4(((const float4*)W)[j], (__nv_bfloat162*)g_whi, (__nv_bfloat162*)g_wlo, j);
    }
}

// ---------------- bf16x3 GEMM via mma.sync ----------------
// CTA 128x128x16, 8 warps of 64x32, 3-stage cp.async pipeline, 48 KB smem,
// 2 CTAs/SM via __launch_bounds__.
#define BK      16
#define KITERS  (IN_DIM / BK)       // 64
#define TILE_B  (128 * BK * 2)      // 4096 B per tile
#define STAGE_B (4 * TILE_B)        // Ahi, Alo, Bhi, Blo = 16 KB
#define STAGES  3
#define SMEM_DYN (STAGES * STAGE_B) // 49152 B = 48 KB (default limit)

// swizzled byte offset inside one tile: 32B rows, granule kg in 0..1
__device__ __forceinline__ uint32_t swz16(int row, int kg) {
    return (uint32_t)(row * 32 + ((kg ^ ((row >> 2) & 1)) << 4));
}

__device__ __forceinline__ void ld_tile(uint32_t dst, const __nv_bfloat16* src,
                                        int k0, int tid) {
    int r  = tid >> 1;          // 0..127
    int kg = tid & 1;           // 0..1
    cp16(dst + swz16(r, kg), src + (size_t)r * IN_DIM + k0 + kg * 8);
}

__global__ __launch_bounds__(256, 2) void gemm_bf16x3_kernel() {
    extern __shared__ char dsm[];
    const int tid  = threadIdx.x;
    const int wid  = tid >> 5;
    const int lane = tid & 31;
    const int bm = blockIdx.y * 128;
    const int bn = blockIdx.x * 128;
    const int warpM = (wid >> 2) * 64;   // 0 or 64
    const int warpN = (wid & 3) * 32;    // 0,32,64,96

    const uint32_t sbase = smem_u32(dsm);

    const __nv_bfloat16* xh = g_xhi + (size_t)bm * IN_DIM;
    const __nv_bfloat16* xl = g_xlo + (size_t)bm * IN_DIM;
    const __nv_bfloat16* wh = g_whi + (size_t)bn * IN_DIM;
    const __nv_bfloat16* wl = g_wlo + (size_t)bn * IN_DIM;

    // prologue: fill stages 0 and 1
#pragma unroll
    for (int s = 0; s < 2; s++) {
        uint32_t sb = sbase + s * STAGE_B;
        ld_tile(sb + 0 * TILE_B, xh, s * BK, tid);
        ld_tile(sb + 1 * TILE_B, xl, s * BK, tid);
        ld_tile(sb + 2 * TILE_B, wh, s * BK, tid);
        ld_tile(sb + 3 * TILE_B, wl, s * BK, tid);
        asm volatile("cp.async.commit_group;" ::: "memory");
    }

    float acc[4][4][4];
#pragma unroll
    for (int m = 0; m < 4; m++)
#pragma unroll
        for (int n = 0; n < 4; n++)
#pragma unroll
            for (int q = 0; q < 4; q++) acc[m][n][q] = 0.f;

    // per-lane ldmatrix address components (m16n8k16 fragment maps)
    const int arow = warpM + (lane & 7) + ((lane >> 3) & 1) * 8;
    const int akg  = lane >> 4;
    const int brow = warpN + (lane & 7) + (lane >> 4) * 8;
    const int bkg  = (lane >> 3) & 1;

    for (int i = 0; i < KITERS; i++) {
        const uint32_t sb = sbase + (i % STAGES) * STAGE_B;

        if (i == KITERS - 1) asm volatile("cp.async.wait_group 0;" ::: "memory");
        else                 asm volatile("cp.async.wait_group 1;" ::: "memory");
        __syncthreads();

        // prefetch i+2 into the slot freed by i-1
        if (i + 2 < KITERS) {
            uint32_t pb = sbase + ((i + 2) % STAGES) * STAGE_B;
            const int kn = (i + 2) * BK;
            ld_tile(pb + 0 * TILE_B, xh, kn, tid);
            ld_tile(pb + 1 * TILE_B, xl, kn, tid);
            ld_tile(pb + 2 * TILE_B, wh, kn, tid);
            ld_tile(pb + 3 * TILE_B, wl, kn, tid);
            asm volatile("cp.async.commit_group;" ::: "memory");
        }

        const uint32_t As = sb + 0 * TILE_B;
        const uint32_t Al = sb + 1 * TILE_B;
        const uint32_t Bs = sb + 2 * TILE_B;
        const uint32_t Bl = sb + 3 * TILE_B;

        // B fragments: resident for the whole iter (16 regs)
        uint32_t bhi[2][4], blo[2][4];
#pragma unroll
        for (int np = 0; np < 2; np++) {
            int r = brow + np * 16;
            ldsm4(bhi[np], Bs + swz16(r, bkg));
            ldsm4(blo[np], Bl + swz16(r, bkg));
        }

        // A fragments: double-buffered per m (16 regs live)
        uint32_t ah[2][4], al[2][4];
        ldsm4(ah[0], As + swz16(arow, akg));
        ldsm4(al[0], Al + swz16(arow, akg));
#pragma unroll
        for (int m = 0; m < 4; m++) {
            const int cur = m & 1;
            if (m < 3) {
                int r = arow + (m + 1) * 16;
                ldsm4(ah[cur ^ 1], As + swz16(r, akg));
                ldsm4(al[cur ^ 1], Al + swz16(r, akg));
            }
#pragma unroll
            for (int np = 0; np < 2; np++)
#pragma unroll
                for (int h = 0; h < 2; h++) {
                    float* c = acc[m][np * 2 + h];
                    mma16816(c, ah[cur], &bhi[np][h * 2]);
                    mma16816(c, ah[cur], &blo[np][h * 2]);
                    mma16816(c, al[cur], &bhi[np][h * 2]);
                }
        }
    }

    // epilogue: direct fp32 stores to g_z
#pragma unroll
    for (int m = 0; m < 4; m++) {
        int row = bm + warpM + m * 16 + (lane >> 2);
#pragma unroll
        for (int n = 0; n < 4; n++) {
            int col = bn + warpN + n * 8 + (lane & 3) * 2;
            *(float2*)(g_z + (size_t)row * OUT_DIM + col) =
                make_float2(acc[m][n][0], acc[m][n][1]);
            *(float2*)(g_z + (size_t)(row + 8) * OUT_DIM + col) =
                make_float2(acc[m][n][2], acc[m][n][3]);
        }
    }
}

// ---------------------------------------------------------------------------
// Batched Householder QR (LAPACK geqrf/orgqr) of 256x3 matrices. (unchanged)
// ---------------------------------------------------------------------------
__device__ __forceinline__ float warp_sum(float v) {
#pragma unroll
    for (int o = 16; o > 0; o >>= 1) v += __shfl_xor_sync(0xffffffffu, v, o);
    return v;
}

__global__ __launch_bounds__(256) void qr_kernel(float* __restrict__ out) {
    const int warp = (blockIdx.x * blockDim.x + threadIdx.x) >> 5;
    const int lane = threadIdx.x & 31;
    if (warp >= B_ROWS) return;

    float4 buf[6];
    const float4* zp = (const float4*)(g_z + (size_t)warp * OUT_DIM) + lane * 6;
#pragma unroll
    for (int i = 0; i < 6; i++) buf[i] = zp[i];
    float* bf = (float*)buf;

    float Mv[8][3];
#pragma unroll
    for (int r = 0; r < 8; r++)
#pragma unroll
        for (int j = 0; j < 3; j++) Mv[r][j] = bf[r * 3 + j];

    const int gr0 = lane * 8;
    float tau[3];

#pragma unroll
    for (int k = 0; k < 3; k++) {
        float ss = 0.f;
#pragma unroll
        for (int r = 0; r < 8; r++) {
            int gr = gr0 + r;
            if (gr >= k) ss += Mv[r][k] * Mv[r][k];
        }
        ss = warp_sum(ss);
        float alpha = __shfl_sync(0xffffffffu, Mv[k][k], 0);
        float nrm = sqrtf(ss);
        float beta = (alpha >= 0.f) ? -nrm : nrm;
        float t = (nrm > 0.f) ? (beta - alpha) / beta : 0.f;
        tau[k] = t;
        float inv = (nrm > 0.f) ? 1.0f / (alpha - beta) : 0.f;
#pragma unroll
        for (int r = 0; r < 8; r++) {
            int gr = gr0 + r;
            if (gr > k) Mv[r][k] *= inv;
        }
#pragma unroll
        for (int j = 0; j < 3; j++) {
            if (j <= k) continue;
            float d = 0.f;
#pragma unroll
            for (int r = 0; r < 8; r++) {
                int gr = gr0 + r;
                if (gr > k)       d += Mv[r][k] * Mv[r][j];
                else if (gr == k) d += Mv[r][j];
            }
            d = warp_sum(d);
            float td = t * d;
#pragma unroll
            for (int r = 0; r < 8; r++) {
                int gr = gr0 + r;
                if (gr > k)       Mv[r][j] -= td * Mv[r][k];
                else if (gr == k) Mv[r][j] -= td;
            }
        }
    }

    float Q[8][3];
#pragma unroll
    for (int r = 0; r < 8; r++)
#pragma unroll
        for (int j = 0; j < 3; j++) Q[r][j] = (gr0 + r == j) ? 1.f : 0.f;

#pragma unroll
    for (int k = 2; k >= 0; k--) {
        float d[3];
#pragma unroll
        for (int j = 0; j < 3; j++) {
            float s = 0.f;
#pragma unroll
            for (int r = 0; r < 8; r++) {
                int gr = gr0 + r;
                if (gr > k)       s += Mv[r][k] * Q[r][j];
                else if (gr == k) s += Q[r][j];
            }
            d[j] = warp_sum(s) * tau[k];
        }
#pragma unroll
        for (int j = 0; j < 3; j++) {
#pragma unroll
            for (int r = 0; r < 8; r++) {
                int gr = gr0 + r;
                if (gr > k)       Q[r][j] -= d[j] * Mv[r][k];
                else if (gr == k) Q[r][j] -= d[j];
            }
        }
    }

#pragma unroll
    for (int r = 0; r < 8; r++)
#pragma unroll
        for (int j = 0; j < 3; j++) bf[r * 3 + j] = Q[r][j];
    float4* op = (float4*)(out + (size_t)warp * OUT_DIM) + lane * 6;
#pragma unroll
    for (int i = 0; i < 6; i++) op[i] = buf[i];
}

// ---------------------------------------------------------------------------
// kernel_launch: ONLY kernel launches — no runtime API calls of any kind.
// ---------------------------------------------------------------------------
extern "C" void kernel_launch(void* const* d_in, const int* in_sizes, int n_in,
                              void* d_out, int out_size) {
    const float* x = (const float*)d_in[0];   // (16384, 1024) fp32
    const float* W = (const float*)d_in[1];   // (768, 1024) fp32
    float* out = (float*)d_out;               // (16384, 768) fp32

    split_all_kernel<<<(N4X + N4W + 255) / 256, 256>>>(x, W);

    dim3 grid(OUT_DIM / 128, B_ROWS / 128);   // (6, 128)
    gemm_bf16x3_kernel<<<grid, 256, SMEM_DYN>>>();

    qr_kernel<<<2048, 256>>>(out);
}

// round 11
// speedup vs baseline: 2.6742x; 1.1976x over previous
#include <cuda_runtime.h>
#include <cuda_bf16.h>
#include <cstdint>

#define B_ROWS  16384
#define IN_DIM  1024
#define OUT_DIM 768

// ---------------- device scratch (allocation-free rule) ----------------
__device__ __align__(16) float         g_z[B_ROWS * OUT_DIM];      // 48 MB
__device__ __align__(16) __nv_bfloat16 g_xhi[B_ROWS * IN_DIM];     // 32 MB
__device__ __align__(16) __nv_bfloat16 g_xlo[B_ROWS * IN_DIM];     // 32 MB
__device__ __align__(16) __nv_bfloat16 g_whi[OUT_DIM * IN_DIM];    // 1.5 MB
__device__ __align__(16) __nv_bfloat16 g_wlo[OUT_DIM * IN_DIM];    // 1.5 MB

// ---------------- helpers ----------------
__device__ __forceinline__ uint32_t smem_u32(const void* p) {
    uint32_t a;
    asm("{ .reg .u64 t; cvta.to.shared.u64 t, %1; cvt.u32.u64 %0, t; }" : "=r"(a) : "l"(p));
    return a;
}
__device__ __forceinline__ void cp16(uint32_t dst, const void* src) {
    asm volatile("cp.async.cg.shared.global [%0], [%1], 16;" :: "r"(dst), "l"(src));
}
__device__ __forceinline__ void ldsm4(uint32_t* r, uint32_t addr) {
    asm volatile("ldmatrix.sync.aligned.m8n8.x4.shared.b16 {%0,%1,%2,%3}, [%4];"
                 : "=r"(r[0]), "=r"(r[1]), "=r"(r[2]), "=r"(r[3]) : "r"(addr));
}
__device__ __forceinline__ void mma16816(float* c, const uint32_t* a, const uint32_t* b) {
    asm volatile(
        "mma.sync.aligned.m16n8k16.row.col.f32.bf16.bf16.f32 "
        "{%0,%1,%2,%3}, {%4,%5,%6,%7}, {%8,%9}, {%0,%1,%2,%3};"
        : "+f"(c[0]), "+f"(c[1]), "+f"(c[2]), "+f"(c[3])
        : "r"(a[0]), "r"(a[1]), "r"(a[2]), "r"(a[3]), "r"(b[0]), "r"(b[1]));
}

__device__ __forceinline__ void split4(float4 v, __nv_bfloat162* hp, __nv_bfloat162* lp, int i) {
    __nv_bfloat16 h0 = __float2bfloat16_rn(v.x);
    __nv_bfloat16 h1 = __float2bfloat16_rn(v.y);
    __nv_bfloat16 h2 = __float2bfloat16_rn(v.z);
    __nv_bfloat16 h3 = __float2bfloat16_rn(v.w);
    __nv_bfloat16 l0 = __float2bfloat16_rn(v.x - __bfloat162float(h0));
    __nv_bfloat16 l1 = __float2bfloat16_rn(v.y - __bfloat162float(h1));
    __nv_bfloat16 l2 = __float2bfloat16_rn(v.z - __bfloat162float(h2));
    __nv_bfloat16 l3 = __float2bfloat16_rn(v.w - __bfloat162float(h3));
    hp[2 * i]     = __nv_bfloat162(h0, h1);
    hp[2 * i + 1] = __nv_bfloat162(h2, h3);
    lp[2 * i]     = __nv_bfloat162(l0, l1);
    lp[2 * i + 1] = __nv_bfloat162(l2, l3);
}

#define N4X (B_ROWS * IN_DIM / 4)
#define N4W (OUT_DIM * IN_DIM / 4)
__global__ __launch_bounds__(256) void split_all_kernel(const float* __restrict__ x,
                                                        const float* __restrict__ W) {
    int i = blockIdx.x * blockDim.x + threadIdx.x;
    if (i < N4X) {
        split4(((const float4*)x)[i], (__nv_bfloat162*)g_xhi, (__nv_bfloat162*)g_xlo, i);
    } else if (i < N4X + N4W) {
        int j = i - N4X;
        split4(((const float4*)W)[j], (__nv_bfloat162*)g_whi, (__nv_bfloat162*)g_wlo, j);
    }
}

// ---------------- bf16x3 GEMM via mma.sync ----------------
// CTA 128x128x16, 4 warps of 64x64, 3-stage cp.async pipeline, 48 KB smem.
// Wider warp tile cuts LDSM-per-MMA 1.5x -> smem port no longer binding.
#define BK      16
#define KITERS  (IN_DIM / BK)       // 64
#define TILE_B  (128 * BK * 2)      // 4096 B per tile
#define STAGE_B (4 * TILE_B)        // Ahi, Alo, Bhi, Blo = 16 KB
#define STAGES  3
#define SMEM_DYN (STAGES * STAGE_B) // 49152 B = 48 KB (default limit)

// swizzled byte offset inside one tile: 32B rows, granule kg in 0..1
__device__ __forceinline__ uint32_t swz16(int row, int kg) {
    return (uint32_t)(row * 32 + ((kg ^ ((row >> 2) & 1)) << 4));
}

// 128 threads: each loads 2 granules of a 128-row tile
__device__ __forceinline__ void ld_tile(uint32_t dst, const __nv_bfloat16* src,
                                        int k0, int tid) {
#pragma unroll
    for (int i = 0; i < 2; i++) {
        int gid = tid + i * 128;        // 0..255
        int r   = gid >> 1;
        int kg  = gid & 1;
        cp16(dst + swz16(r, kg), src + (size_t)r * IN_DIM + k0 + kg * 8);
    }
}

__global__ __launch_bounds__(128, 2) void gemm_bf16x3_kernel() {
    extern __shared__ char dsm[];
    const int tid  = threadIdx.x;
    const int wid  = tid >> 5;
    const int lane = tid & 31;
    const int bm = blockIdx.y * 128;
    const int bn = blockIdx.x * 128;
    const int warpM = (wid >> 1) * 64;   // 0 or 64
    const int warpN = (wid & 1) * 64;    // 0 or 64

    const uint32_t sbase = smem_u32(dsm);

    const __nv_bfloat16* xh = g_xhi + (size_t)bm * IN_DIM;
    const __nv_bfloat16* xl = g_xlo + (size_t)bm * IN_DIM;
    const __nv_bfloat16* wh = g_whi + (size_t)bn * IN_DIM;
    const __nv_bfloat16* wl = g_wlo + (size_t)bn * IN_DIM;

    // prologue: fill stages 0 and 1
#pragma unroll
    for (int s = 0; s < 2; s++) {
        uint32_t sb = sbase + s * STAGE_B;
        ld_tile(sb + 0 * TILE_B, xh, s * BK, tid);
        ld_tile(sb + 1 * TILE_B, xl, s * BK, tid);
        ld_tile(sb + 2 * TILE_B, wh, s * BK, tid);
        ld_tile(sb + 3 * TILE_B, wl, s * BK, tid);
        asm volatile("cp.async.commit_group;" ::: "memory");
    }

    // acc[m-atom][n8-col][quad] : 4 x 8 x 4 = 128 fp32
    float acc[4][8][4];
#pragma unroll
    for (int m = 0; m < 4; m++)
#pragma unroll
        for (int n = 0; n < 8; n++)
#pragma unroll
            for (int q = 0; q < 4; q++) acc[m][n][q] = 0.f;

    // per-lane ldmatrix address components (m16n8k16 fragment maps)
    const int arow = warpM + (lane & 7) + ((lane >> 3) & 1) * 8;
    const int akg  = lane >> 4;
    const int brow = warpN + (lane & 7) + (lane >> 4) * 8;
    const int bkg  = (lane >> 3) & 1;

    for (int i = 0; i < KITERS; i++) {
        const uint32_t sb = sbase + (i % STAGES) * STAGE_B;

        if (i == KITERS - 1) asm volatile("cp.async.wait_group 0;" ::: "memory");
        else                 asm volatile("cp.async.wait_group 1;" ::: "memory");
        __syncthreads();

        // prefetch i+2 into the slot freed by i-1
        if (i + 2 < KITERS) {
            uint32_t pb = sbase + ((i + 2) % STAGES) * STAGE_B;
            const int kn = (i + 2) * BK;
            ld_tile(pb + 0 * TILE_B, xh, kn, tid);
            ld_tile(pb + 1 * TILE_B, xl, kn, tid);
            ld_tile(pb + 2 * TILE_B, wh, kn, tid);
            ld_tile(pb + 3 * TILE_B, wl, kn, tid);
            asm volatile("cp.async.commit_group;" ::: "memory");
        }

        const uint32_t As = sb + 0 * TILE_B;
        const uint32_t Al = sb + 1 * TILE_B;
        const uint32_t Bs = sb + 2 * TILE_B;
        const uint32_t Bl = sb + 3 * TILE_B;

        // B fragments: 4 n-atoms x (hi,lo), resident for whole iter (32 regs)
        uint32_t bhi[4][4], blo[4][4];
#pragma unroll
        for (int na = 0; na < 4; na++) {
            int r = brow + na * 16;
            ldsm4(bhi[na], Bs + swz16(r, bkg));
            ldsm4(blo[na], Bl + swz16(r, bkg));
        }

#pragma unroll
        for (int m = 0; m < 4; m++) {
            uint32_t ah[4], al[4];
            int r = arow + m * 16;
            ldsm4(ah, As + swz16(r, akg));
            ldsm4(al, Al + swz16(r, akg));
#pragma unroll
            for (int na = 0; na < 4; na++)
#pragma unroll
                for (int h = 0; h < 2; h++) {
                    float* c = acc[m][na * 2 + h];
                    mma16816(c, ah, &bhi[na][h * 2]);
                    mma16816(c, ah, &blo[na][h * 2]);
                    mma16816(c, al, &bhi[na][h * 2]);
                }
        }
    }

    // epilogue: direct fp32 stores to g_z
#pragma unroll
    for (int m = 0; m < 4; m++) {
        int row = bm + warpM + m * 16 + (lane >> 2);
#pragma unroll
        for (int n = 0; n < 8; n++) {
            int col = bn + warpN + n * 8 + (lane & 3) * 2;
            *(float2*)(g_z + (size_t)row * OUT_DIM + col) =
                make_float2(acc[m][n][0], acc[m][n][1]);
            *(float2*)(g_z + (size_t)(row + 8) * OUT_DIM + col) =
                make_float2(acc[m][n][2], acc[m][n][3]);
        }
    }
}

// ---------------------------------------------------------------------------
// Batched Householder QR (LAPACK geqrf/orgqr) of 256x3 matrices. (unchanged)
// ---------------------------------------------------------------------------
__device__ __forceinline__ float warp_sum(float v) {
#pragma unroll
    for (int o = 16; o > 0; o >>= 1) v += __shfl_xor_sync(0xffffffffu, v, o);
    return v;
}

__global__ __launch_bounds__(256) void qr_kernel(float* __restrict__ out) {
    const int warp = (blockIdx.x * blockDim.x + threadIdx.x) >> 5;
    const int lane = threadIdx.x & 31;
    if (warp >= B_ROWS) return;

    float4 buf[6];
    const float4* zp = (const float4*)(g_z + (size_t)warp * OUT_DIM) + lane * 6;
#pragma unroll
    for (int i = 0; i < 6; i++) buf[i] = zp[i];
    float* bf = (float*)buf;

    float Mv[8][3];
#pragma unroll
    for (int r = 0; r < 8; r++)
#pragma unroll
        for (int j = 0; j < 3; j++) Mv[r][j] = bf[r * 3 + j];

    const int gr0 = lane * 8;
    float tau[3];

#pragma unroll
    for (int k = 0; k < 3; k++) {
        float ss = 0.f;
#pragma unroll
        for (int r = 0; r < 8; r++) {
            int gr = gr0 + r;
            if (gr >= k) ss += Mv[r][k] * Mv[r][k];
        }
        ss = warp_sum(ss);
        float alpha = __shfl_sync(0xffffffffu, Mv[k][k], 0);
        float nrm = sqrtf(ss);
        float beta = (alpha >= 0.f) ? -nrm : nrm;
        float t = (nrm > 0.f) ? (beta - alpha) / beta : 0.f;
        tau[k] = t;
        float inv = (nrm > 0.f) ? 1.0f / (alpha - beta) : 0.f;
#pragma unroll
        for (int r = 0; r < 8; r++) {
            int gr = gr0 + r;
            if (gr > k) Mv[r][k] *= inv;
        }
#pragma unroll
        for (int j = 0; j < 3; j++) {
            if (j <= k) continue;
            float d = 0.f;
#pragma unroll
            for (int r = 0; r < 8; r++) {
                int gr = gr0 + r;
                if (gr > k)       d += Mv[r][k] * Mv[r][j];
                else if (gr == k) d += Mv[r][j];
            }
            d = warp_sum(d);
            float td = t * d;
#pragma unroll
            for (int r = 0; r < 8; r++) {
                int gr = gr0 + r;
                if (gr > k)       Mv[r][j] -= td * Mv[r][k];
                else if (gr == k) Mv[r][j] -= td;
            }
        }
    }

    float Q[8][3];
#pragma unroll
    for (int r = 0; r < 8; r++)
#pragma unroll
        for (int j = 0; j < 3; j++) Q[r][j] = (gr0 + r == j) ? 1.f : 0.f;

#pragma unroll
    for (int k = 2; k >= 0; k--) {
        float d[3];
#pragma unroll
        for (int j = 0; j < 3; j++) {
            float s = 0.f;
#pragma unroll
            for (int r = 0; r < 8; r++) {
                int gr = gr0 + r;
                if (gr > k)       s += Mv[r][k] * Q[r][j];
                else if (gr == k) s += Q[r][j];
            }
            d[j] = warp_sum(s) * tau[k];
        }
#pragma unroll
        for (int j = 0; j < 3; j++) {
#pragma unroll
            for (int r = 0; r < 8; r++) {
                int gr = gr0 + r;
                if (gr > k)       Q[r][j] -= d[j] * Mv[r][k];
                else if (gr == k) Q[r][j] -= d[j];
            }
        }
    }

#pragma unroll
    for (int r = 0; r < 8; r++)
#pragma unroll
        for (int j = 0; j < 3; j++) bf[r * 3 + j] = Q[r][j];
    float4* op = (float4*)(out + (size_t)warp * OUT_DIM) + lane * 6;
#pragma unroll
    for (int i = 0; i < 6; i++) op[i] = buf[i];
}

// ---------------------------------------------------------------------------
// kernel_launch: ONLY kernel launches — no runtime API calls of any kind.
// ---------------------------------------------------------------------------
extern "C" void kernel_launch(void* const* d_in, const int* in_sizes, int n_in,
                              void* d_out, int out_size) {
    const float* x = (const float*)d_in[0];   // (16384, 1024) fp32
    const float* W = (const float*)d_in[1];   // (768, 1024) fp32
    float* out = (float*)d_out;               // (16384, 768) fp32

    split_all_kernel<<<(N4X + N4W + 255) / 256, 256>>>(x, W);

    dim3 grid(OUT_DIM / 128, B_ROWS / 128);   // (6, 128)
    gemm_bf16x3_kernel<<<grid, 128, SMEM_DYN>>>();

    qr_kernel<<<2048, 256>>>(out);
}